// round 15
// baseline (speedup 1.0000x reference)
#include <cuda_runtime.h>
#include <cuda_bf16.h>

using u32 = unsigned int; using u64 = unsigned long long;
#define TPB 512
constexpr int WSZ = 7, HIMG = 56, NPIX = 3136, CDIM = 128;
constexpr float SCALE_F = 0.25f, LN_EPS = 1e-5f;

// smem layout (bytes)
constexpr int AST = 272;                      // tile row stride (136 bf16)
constexpr int WST = 144;                      // W tile row stride
constexpr int TILE = 17408;                   // one 64-row tile
constexpr int OFF_XH = 0, OFF_XL = TILE;      // X tiles; reused as attn-out A2
constexpr int WBUFSZ = 36864;                 // hi plane + lo plane (18432 each)
constexpr int OFF_W0 = 34816;                 // W double buffers
constexpr int WLO = 18432;                    // lo-plane offset within a W buffer
constexpr int OFF_Q = 108544;                 // Qh,Ql,Kh,Kl,Vh,Vl tiles
constexpr int OFF_K = OFF_Q + 2 * TILE;
constexpr int OFF_V = OFF_Q + 4 * TILE;
constexpr int SMEM_BYTES = OFF_Q + 6 * TILE;  // 212992

// precomputed split-bf16 weights (written by prep kernel)
__device__ __nv_bfloat16 d_wqH[49152], d_wqL[49152], d_woH[16384], d_woL[16384];

__global__ void prep_w_kernel(const float* __restrict__ wqkv, const float* __restrict__ wout) {
    int i = blockIdx.x * 256 + threadIdx.x;
    if (i < 49152) {
        float v = wqkv[i];
        __nv_bfloat16 h = __float2bfloat16(v);
        d_wqH[i] = h; d_wqL[i] = __float2bfloat16(v - __bfloat162float(h));
    } else {
        int j = i - 49152;
        float v = wout[j];
        __nv_bfloat16 h = __float2bfloat16(v);
        d_woH[j] = h; d_woL[j] = __float2bfloat16(v - __bfloat162float(h));
    }
}

__device__ __forceinline__ u32 smem_u32(const void* p) {
    u32 a; asm("{ .reg .u64 t; cvta.to.shared.u64 t, %1; cvt.u32.u64 %0, t; }" : "=r"(a) : "l"(p));
    return a;
}
__device__ __forceinline__ u64 gaddr(const void* p) {
    u64 g; asm("cvta.to.global.u64 %0, %1;" : "=l"(g) : "l"(p)); return g;
}
#define CP16(d, s)   asm volatile("cp.async.cg.shared.global [%0], [%1], 16;" :: "r"(d), "l"(s) : "memory")
#define CP_COMMIT()  asm volatile("cp.async.commit_group;" ::: "memory")
#define CP_WAIT(N)   asm volatile("cp.async.wait_group %0;" :: "n"(N) : "memory")

__device__ __forceinline__ void split2(float a, float b, u32& hi, u32& lo) {
    __nv_bfloat16 ha = __float2bfloat16(a), hb = __float2bfloat16(b);
    __nv_bfloat16 la = __float2bfloat16(a - __bfloat162float(ha));
    __nv_bfloat16 lb = __float2bfloat16(b - __bfloat162float(hb));
    hi = (u32)__bfloat16_as_ushort(ha) | ((u32)__bfloat16_as_ushort(hb) << 16);
    lo = (u32)__bfloat16_as_ushort(la) | ((u32)__bfloat16_as_ushort(lb) << 16);
}
// MUFU-free e^x
__device__ __forceinline__ float fexp(float x) {
    float y = fminf(fmaxf(x * 1.44269504f, -126.f), 126.f);
    int ni = __float2int_rn(y);
    float f = y - (float)ni;
    float p = 1.33336e-3f;
    p = fmaf(p, f, 9.61813e-3f);
    p = fmaf(p, f, 5.550411e-2f);
    p = fmaf(p, f, 2.4022651e-1f);
    p = fmaf(p, f, 6.9314718e-1f);
    p = fmaf(p, f, 1.0f);
    return p * __int_as_float((ni + 127) << 23);
}
__device__ __forceinline__ void ldsm4(u32 a[4], u32 addr) {
    asm volatile("ldmatrix.sync.aligned.m8n8.x4.shared.b16 {%0,%1,%2,%3},[%4];"
        : "=r"(a[0]), "=r"(a[1]), "=r"(a[2]), "=r"(a[3]) : "r"(addr));
}
__device__ __forceinline__ void ldsm2t(u32 b[2], u32 addr) {
    asm volatile("ldmatrix.sync.aligned.m8n8.x2.trans.shared.b16 {%0,%1},[%2];"
        : "=r"(b[0]), "=r"(b[1]) : "r"(addr));
}
__device__ __forceinline__ void ldsm2(u32 b[2], u32 addr) {
    asm volatile("ldmatrix.sync.aligned.m8n8.x2.shared.b16 {%0,%1},[%2];"
        : "=r"(b[0]), "=r"(b[1]) : "r"(addr));
}
__device__ __forceinline__ void mma16816(float d[4], const u32 a[4], const u32 b[2]) {
    asm volatile("mma.sync.aligned.m16n8k16.row.col.f32.bf16.bf16.f32 "
        "{%0,%1,%2,%3},{%4,%5,%6,%7},{%8,%9},{%0,%1,%2,%3};"
        : "+f"(d[0]), "+f"(d[1]), "+f"(d[2]), "+f"(d[3])
        : "r"(a[0]), "r"(a[1]), "r"(a[2]), "r"(a[3]), "r"(b[0]), "r"(b[1]));
}
// async-copy one W chunk [128k x 64n] (hi+lo planes) into smem buffer
__device__ __forceinline__ void cp_w(u32 wbase, const __nv_bfloat16* Hp, const __nv_bfloat16* Lp,
                                     int ldw, int cb, int tid) {
    #pragma unroll
    for (int i = 0; i < 2; ++i) {
        int f = tid + i * TPB;
        int k = f >> 3, n8 = f & 7;
        u32 dst = wbase + k * WST + n8 * 16;
        CP16(dst, gaddr(Hp + k * ldw + cb + n8 * 8));
        CP16(dst + WLO, gaddr(Lp + k * ldw + cb + n8 * 8));
    }
}
// C[64x64] chunk; 16 warps, warp tile 16x16.
// 3 independent accumulator sets per nt (one per split term) -> 6 mma chains/warp.
__device__ __forceinline__ void gemm_chunk(u32 smb, u32 wbase, int lane, int mband, int nq,
                                           float d[2][4]) {
    float dhh[2][4] = {}, dhl[2][4] = {}, dlh[2][4] = {};
    u32 aH = smb + OFF_XH + (mband * 16 + (lane & 15)) * AST + (lane >> 4) * 16;
    u32 bRow = wbase + (lane & 15) * WST + nq * 32;
    #pragma unroll
    for (int ks = 0; ks < 8; ++ks) {
        u32 ah[4], al[4];
        ldsm4(ah, aH + ks * 32);
        ldsm4(al, aH + ks * 32 + TILE);
        #pragma unroll
        for (int nt = 0; nt < 2; ++nt) {
            u32 bh[2], bl[2];
            u32 ba = bRow + ks * 16 * WST + nt * 16;
            ldsm2t(bh, ba);
            ldsm2t(bl, ba + WLO);
            mma16816(dhh[nt], ah, bh);
            mma16816(dhl[nt], ah, bl);
            mma16816(dlh[nt], al, bh);
        }
    }
    #pragma unroll
    for (int nt = 0; nt < 2; ++nt)
        #pragma unroll
        for (int i = 0; i < 4; ++i)
            d[nt][i] = dhh[nt][i] + dhl[nt][i] + dlh[nt][i];
}

__global__ __launch_bounds__(TPB, 1)
void swin_mma_kernel(const float* __restrict__ x,
                     const float* __restrict__ ln_g, const float* __restrict__ ln_b,
                     const float* __restrict__ bqkv, const float* __restrict__ bout,
                     float* __restrict__ out) {
    extern __shared__ char smc[];
    const u32 smb = smem_u32(smc);
    const int tid = threadIdx.x, wid = tid >> 5, lane = tid & 31;
    const int w = blockIdx.x, b = w >> 6, wy = (w >> 3) & 7, wx = w & 7;

    // prefetch W chunks 0,1 (overlaps LN below)
    cp_w(smb + OFF_W0,          d_wqH, d_wqL, 384, 0,  tid); CP_COMMIT();
    cp_w(smb + OFF_W0 + WBUFSZ, d_wqH, d_wqL, 384, 64, tid); CP_COMMIT();

    // zero V-tile pad rows 49..63
    if (tid < 480) {
        int t = tid, tile = t / 240, rem = t % 240;
        int row = 49 + rem / 16, q16 = (rem & 15) * 16;
        *reinterpret_cast<uint4*>(smc + OFF_V + tile * TILE + row * AST + q16) =
            make_uint4(0, 0, 0, 0);
    }
    // ---- Phase A: LayerNorm -> split-bf16 X tiles ----
    {
        float4 gg = *reinterpret_cast<const float4*>(&ln_g[lane * 4]);
        float4 bb = *reinterpret_cast<const float4*>(&ln_b[lane * 4]);
        for (int t = wid; t < 49; t += 16) {
            int r = wy * WSZ + t / WSZ, cp = wx * WSZ + t % WSZ;
            const float* xr = x + (size_t)(b * NPIX + r * HIMG + cp) * CDIM;
            float4 v = *reinterpret_cast<const float4*>(&xr[lane * 4]);
            float s = v.x + v.y + v.z + v.w;
            float q = v.x * v.x + v.y * v.y + v.z * v.z + v.w * v.w;
            #pragma unroll
            for (int o = 16; o; o >>= 1) {
                s += __shfl_xor_sync(0xffffffffu, s, o);
                q += __shfl_xor_sync(0xffffffffu, q, o);
            }
            float mu = s * (1.f / 128.f);
            float rs = rsqrtf(q * (1.f / 128.f) - mu * mu + LN_EPS);
            u32 h0, l0, h1, l1;
            split2((v.x - mu) * rs * gg.x + bb.x, (v.y - mu) * rs * gg.y + bb.y, h0, l0);
            split2((v.z - mu) * rs * gg.z + bb.z, (v.w - mu) * rs * gg.w + bb.w, h1, l1);
            char* p = smc + t * AST + lane * 8;
            *reinterpret_cast<uint2*>(p + OFF_XH) = make_uint2(h0, h1);
            *reinterpret_cast<uint2*>(p + OFF_XL) = make_uint2(l0, l1);
        }
    }
    __syncthreads();

    const int mband = wid >> 2, nq = wid & 3, tig = lane & 3, g = lane >> 2;

    // ---- Phase B: QKV GEMM, 6 chunks N=64, cp.async double-buffered ----
    for (int ch = 0; ch < 6; ++ch) {
        u32 wbase = smb + OFF_W0 + (ch & 1) * WBUFSZ;
        if (ch < 5) { CP_WAIT(1); } else { CP_WAIT(0); }
        __syncthreads();
        float d[2][4];
        gemm_chunk(smb, wbase, lane, mband, nq, d);
        int R0 = mband * 16 + g, R1 = R0 + 8;
        #pragma unroll
        for (int nt = 0; nt < 2; ++nt) {
            int n = ch * 64 + nq * 16 + nt * 8 + 2 * tig;
            int base = OFF_Q + (n >> 7) * 2 * TILE, col = n & 127;
            float2 bq = *reinterpret_cast<const float2*>(bqkv + n);
            if (R0 < 49) {
                u32 uh, ul;
                split2(d[nt][0] + bq.x, d[nt][1] + bq.y, uh, ul);
                char* p = smc + base + R0 * AST + col * 2;
                *reinterpret_cast<u32*>(p) = uh;
                *reinterpret_cast<u32*>(p + TILE) = ul;
            }
            if (R1 < 49) {
                u32 uh, ul;
                split2(d[nt][2] + bq.x, d[nt][3] + bq.y, uh, ul);
                char* p = smc + base + R1 * AST + col * 2;
                *reinterpret_cast<u32*>(p) = uh;
                *reinterpret_cast<u32*>(p + TILE) = ul;
            }
        }
        __syncthreads();
        if (ch < 4) { cp_w(wbase, d_wqH, d_wqL, 384, (ch + 2) * 64, tid); CP_COMMIT(); }
    }
    // prefetch both wout chunks; they complete under the attention phase
    cp_w(smb + OFF_W0,          d_woH, d_woL, 128, 0,  tid); CP_COMMIT();
    cp_w(smb + OFF_W0 + WBUFSZ, d_woH, d_woL, 128, 64, tid); CP_COMMIT();

    // ---- Phase C: tensor-core attention; warp = (head, 2 q-bands) ----
    {
        const int head = wid & 7, half = wid >> 3;
        #pragma unroll
        for (int band = 0; band < 2; ++band) {
            int m0 = (half * 2 + band) * 16;
            u32 qh[4], ql[4];
            u32 aaddr = smb + OFF_Q + (m0 + (lane & 15)) * AST + head * 32 + (lane >> 4) * 16;
            ldsm4(qh, aaddr);
            ldsm4(ql, aaddr + TILE);
            float sd[7][4];
            #pragma unroll
            for (int nt = 0; nt < 7; ++nt) { sd[nt][0]=sd[nt][1]=sd[nt][2]=sd[nt][3]=0.f; }
            u32 baddr = smb + OFF_K + (lane & 7) * AST + head * 32 + ((lane >> 3) & 1) * 16;
            #pragma unroll
            for (int nt = 0; nt < 7; ++nt) {
                u32 bh[2], bl[2];
                ldsm2(bh, baddr + nt * 8 * AST);
                ldsm2(bl, baddr + nt * 8 * AST + TILE);
                mma16816(sd[nt], qh, bh);
                mma16816(sd[nt], qh, bl);
                mma16816(sd[nt], ql, bh);
            }
            float den0 = 0.f, den1 = 0.f;
            u32 Phg[8], Phg8[8], Plg[8], Plg8[8];
            #pragma unroll
            for (int nt = 0; nt < 7; ++nt) {
                float e0 = fexp(sd[nt][0] * SCALE_F);
                float e1 = fexp(sd[nt][1] * SCALE_F);
                float e2 = fexp(sd[nt][2] * SCALE_F);
                float e3 = fexp(sd[nt][3] * SCALE_F);
                if (nt == 6) {
                    bool v0 = tig == 0;
                    e0 = v0 ? e0 : 0.f; e2 = v0 ? e2 : 0.f;
                    e1 = 0.f; e3 = 0.f;
                }
                den0 += e0 + e1; den1 += e2 + e3;
                split2(e0, e1, Phg[nt], Plg[nt]);
                split2(e2, e3, Phg8[nt], Plg8[nt]);
            }
            Phg[7] = Plg[7] = Phg8[7] = Plg8[7] = 0u;
            den0 += __shfl_xor_sync(0xffffffffu, den0, 1);
            den0 += __shfl_xor_sync(0xffffffffu, den0, 2);
            den1 += __shfl_xor_sync(0xffffffffu, den1, 1);
            den1 += __shfl_xor_sync(0xffffffffu, den1, 2);
            // O = P V; 3 independent accumulator sets -> 6 chains
            float ohh[2][4] = {}, ohl[2][4] = {}, olh[2][4] = {};
            #pragma unroll
            for (int kc = 0; kc < 4; ++kc) {
                u32 ah[4] = {Phg[2*kc], Phg8[2*kc], Phg[2*kc+1], Phg8[2*kc+1]};
                u32 al[4] = {Plg[2*kc], Plg8[2*kc], Plg[2*kc+1], Plg8[2*kc+1]};
                u32 vaddr = smb + OFF_V + (kc * 16 + (lane & 15)) * AST + head * 32;
                #pragma unroll
                for (int ntO = 0; ntO < 2; ++ntO) {
                    u32 vh[2], vl[2];
                    ldsm2t(vh, vaddr + ntO * 16);
                    ldsm2t(vl, vaddr + ntO * 16 + TILE);
                    mma16816(ohh[ntO], ah, vh);
                    mma16816(ohl[ntO], ah, vl);
                    mma16816(olh[ntO], al, vh);
                }
            }
            float inv0 = __frcp_rn(den0), inv1 = __frcp_rn(den1);
            int r0 = m0 + g, r1 = r0 + 8;
            #pragma unroll
            for (int ntO = 0; ntO < 2; ++ntO) {
                float o0 = ohh[ntO][0] + ohl[ntO][0] + olh[ntO][0];
                float o1 = ohh[ntO][1] + ohl[ntO][1] + olh[ntO][1];
                float o2 = ohh[ntO][2] + ohl[ntO][2] + olh[ntO][2];
                float o3 = ohh[ntO][3] + ohl[ntO][3] + olh[ntO][3];
                int col = head * 16 + ntO * 8 + 2 * tig;
                if (r0 < 49) {
                    u32 uh, ul;
                    split2(o0 * inv0, o1 * inv0, uh, ul);
                    char* p = smc + r0 * AST + col * 2;
                    *reinterpret_cast<u32*>(p + OFF_XH) = uh;
                    *reinterpret_cast<u32*>(p + OFF_XL) = ul;
                }
                if (r1 < 49) {
                    u32 uh, ul;
                    split2(o2 * inv1, o3 * inv1, uh, ul);
                    char* p = smc + r1 * AST + col * 2;
                    *reinterpret_cast<u32*>(p + OFF_XH) = uh;
                    *reinterpret_cast<u32*>(p + OFF_XL) = ul;
                }
            }
        }
    }
    CP_WAIT(0);
    __syncthreads();

    // ---- Phase D: out-proj, both chunks resident; no inner barriers ----
    #pragma unroll
    for (int ch = 0; ch < 2; ++ch) {
        float d[2][4];
        gemm_chunk(smb, smb + OFF_W0 + ch * WBUFSZ, lane, mband, nq, d);
        int R0 = mband * 16 + g, R1 = R0 + 8;
        #pragma unroll
        for (int nt = 0; nt < 2; ++nt) {
            int n = ch * 64 + nq * 16 + nt * 8 + 2 * tig;
            float2 bo = *reinterpret_cast<const float2*>(bout + n);
            if (R0 < 49) {
                int r = wy * WSZ + R0 / WSZ, cp = wx * WSZ + R0 % WSZ;
                *reinterpret_cast<float2*>(out + (size_t)(b * NPIX + r * HIMG + cp) * CDIM + n) =
                    make_float2(d[nt][0] + bo.x, d[nt][1] + bo.y);
            }
            if (R1 < 49) {
                int r = wy * WSZ + R1 / WSZ, cp = wx * WSZ + R1 % WSZ;
                *reinterpret_cast<float2*>(out + (size_t)(b * NPIX + r * HIMG + cp) * CDIM + n) =
                    make_float2(d[nt][2] + bo.x, d[nt][3] + bo.y);
            }
        }
    }
}

extern "C" void kernel_launch(void* const* d_in, const int* in_sizes, int n_in,
                              void* d_out, int out_size) {
    const float* x    = (const float*)d_in[0];
    const float* g    = (const float*)d_in[1];
    const float* bt   = (const float*)d_in[2];
    const float* wqkv = (const float*)d_in[3];
    const float* bqkv = (const float*)d_in[4];
    const float* wout = (const float*)d_in[5];
    const float* bout = (const float*)d_in[6];
    float* out = (float*)d_out;
    prep_w_kernel<<<256, 256>>>(wqkv, wout);
    cudaFuncSetAttribute(swin_mma_kernel,
                         cudaFuncAttributeMaxDynamicSharedMemorySize, SMEM_BYTES);
    swin_mma_kernel<<<4096, TPB, SMEM_BYTES>>>(x, g, bt, bqkv, bout, out);
}

// round 16
// speedup vs baseline: 1.0707x; 1.0707x over previous
#include <cuda_runtime.h>
#include <cuda_bf16.h>

using u32 = unsigned int; using u64 = unsigned long long;
#define TPB 512
constexpr int WSZ = 7, HIMG = 56, NPIX = 3136, CDIM = 128;
constexpr float SCALE_F = 0.25f, LN_EPS = 1e-5f;

// smem layout (bytes)
constexpr int AST = 272;                      // tile row stride (136 bf16)
constexpr int WST = 144;                      // W tile row stride
constexpr int TILE = 17408;                   // one 64-row tile
constexpr int OFF_XH = 0, OFF_XL = TILE;      // X tiles; reused as attn-out A2
constexpr int WBUFSZ = 36864;                 // hi plane + lo plane (18432 each)
constexpr int OFF_W0 = 34816;                 // W double buffers
constexpr int WLO = 18432;                    // lo-plane offset within a W buffer
constexpr int OFF_Q = 108544;                 // Qh,Ql,Kh,Kl,Vh,Vl tiles
constexpr int OFF_K = OFF_Q + 2 * TILE;
constexpr int OFF_V = OFF_Q + 4 * TILE;
constexpr int SMEM_BYTES = OFF_Q + 6 * TILE;  // 212992

// precomputed split-bf16 weights (written by prep kernel)
__device__ __nv_bfloat16 d_wqH[49152], d_wqL[49152], d_woH[16384], d_woL[16384];

__global__ void prep_w_kernel(const float* __restrict__ wqkv, const float* __restrict__ wout) {
    int i = blockIdx.x * 256 + threadIdx.x;
    if (i < 49152) {
        float v = wqkv[i];
        __nv_bfloat16 h = __float2bfloat16(v);
        d_wqH[i] = h; d_wqL[i] = __float2bfloat16(v - __bfloat162float(h));
    } else {
        int j = i - 49152;
        float v = wout[j];
        __nv_bfloat16 h = __float2bfloat16(v);
        d_woH[j] = h; d_woL[j] = __float2bfloat16(v - __bfloat162float(h));
    }
}

__device__ __forceinline__ u32 smem_u32(const void* p) {
    u32 a; asm("{ .reg .u64 t; cvta.to.shared.u64 t, %1; cvt.u32.u64 %0, t; }" : "=r"(a) : "l"(p));
    return a;
}
__device__ __forceinline__ u64 gaddr(const void* p) {
    u64 g; asm("cvta.to.global.u64 %0, %1;" : "=l"(g) : "l"(p)); return g;
}
#define CP16(d, s)   asm volatile("cp.async.cg.shared.global [%0], [%1], 16;" :: "r"(d), "l"(s) : "memory")
#define CP_COMMIT()  asm volatile("cp.async.commit_group;" ::: "memory")
#define CP_WAIT(N)   asm volatile("cp.async.wait_group %0;" :: "n"(N) : "memory")

__device__ __forceinline__ void split2(float a, float b, u32& hi, u32& lo) {
    __nv_bfloat16 ha = __float2bfloat16(a), hb = __float2bfloat16(b);
    __nv_bfloat16 la = __float2bfloat16(a - __bfloat162float(ha));
    __nv_bfloat16 lb = __float2bfloat16(b - __bfloat162float(hb));
    hi = (u32)__bfloat16_as_ushort(ha) | ((u32)__bfloat16_as_ushort(hb) << 16);
    lo = (u32)__bfloat16_as_ushort(la) | ((u32)__bfloat16_as_ushort(lb) << 16);
}
// MUFU-free e^x
__device__ __forceinline__ float fexp(float x) {
    float y = fminf(fmaxf(x * 1.44269504f, -126.f), 126.f);
    int ni = __float2int_rn(y);
    float f = y - (float)ni;
    float p = 1.33336e-3f;
    p = fmaf(p, f, 9.61813e-3f);
    p = fmaf(p, f, 5.550411e-2f);
    p = fmaf(p, f, 2.4022651e-1f);
    p = fmaf(p, f, 6.9314718e-1f);
    p = fmaf(p, f, 1.0f);
    return p * __int_as_float((ni + 127) << 23);
}
__device__ __forceinline__ void ldsm4(u32 a[4], u32 addr) {
    asm volatile("ldmatrix.sync.aligned.m8n8.x4.shared.b16 {%0,%1,%2,%3},[%4];"
        : "=r"(a[0]), "=r"(a[1]), "=r"(a[2]), "=r"(a[3]) : "r"(addr));
}
__device__ __forceinline__ void ldsm4t(u32 a[4], u32 addr) {
    asm volatile("ldmatrix.sync.aligned.m8n8.x4.trans.shared.b16 {%0,%1,%2,%3},[%4];"
        : "=r"(a[0]), "=r"(a[1]), "=r"(a[2]), "=r"(a[3]) : "r"(addr));
}
__device__ __forceinline__ void ldsm2(u32 b[2], u32 addr) {
    asm volatile("ldmatrix.sync.aligned.m8n8.x2.shared.b16 {%0,%1},[%2];"
        : "=r"(b[0]), "=r"(b[1]) : "r"(addr));
}
__device__ __forceinline__ void mma16816(float d[4], const u32 a[4], const u32 b0, const u32 b1) {
    asm volatile("mma.sync.aligned.m16n8k16.row.col.f32.bf16.bf16.f32 "
        "{%0,%1,%2,%3},{%4,%5,%6,%7},{%8,%9},{%0,%1,%2,%3};"
        : "+f"(d[0]), "+f"(d[1]), "+f"(d[2]), "+f"(d[3])
        : "r"(a[0]), "r"(a[1]), "r"(a[2]), "r"(a[3]), "r"(b0), "r"(b1));
}
// async-copy one W chunk [128k x 64n] (hi+lo planes) into smem buffer
__device__ __forceinline__ void cp_w(u32 wbase, const __nv_bfloat16* Hp, const __nv_bfloat16* Lp,
                                     int ldw, int cb, int tid) {
    #pragma unroll
    for (int i = 0; i < 2; ++i) {
        int f = tid + i * TPB;
        int k = f >> 3, n8 = f & 7;
        u32 dst = wbase + k * WST + n8 * 16;
        CP16(dst, gaddr(Hp + k * ldw + cb + n8 * 8));
        CP16(dst + WLO, gaddr(Lp + k * ldw + cb + n8 * 8));
    }
}
// C[64x64] chunk; 16 warps, warp tile 16x16; single accumulator per nt (R14)
__device__ __forceinline__ void gemm_chunk(u32 smb, u32 wbase, int lane, int mband, int nq,
                                           float d[2][4]) {
    u32 aH = smb + OFF_XH + (mband * 16 + (lane & 15)) * AST + (lane >> 4) * 16;
    // x4 trans B: lanes 0-15 rows ks*16+(lane&15) col nq*32; lanes 16-31 same rows col +16
    u32 bRow = wbase + (lane & 15) * WST + nq * 32 + (lane >> 4) * 16;
    #pragma unroll
    for (int ks = 0; ks < 8; ++ks) {
        u32 ah[4], al[4];
        ldsm4(ah, aH + ks * 32);
        ldsm4(al, aH + ks * 32 + TILE);
        u32 bh[4], bl[4];
        ldsm4t(bh, bRow + ks * 16 * WST);
        ldsm4t(bl, bRow + ks * 16 * WST + WLO);
        #pragma unroll
        for (int nt = 0; nt < 2; ++nt) {
            mma16816(d[nt], ah, bh[2*nt], bh[2*nt+1]);
            mma16816(d[nt], ah, bl[2*nt], bl[2*nt+1]);
            mma16816(d[nt], al, bh[2*nt], bh[2*nt+1]);
        }
    }
}

__global__ __launch_bounds__(TPB, 1)
void swin_mma_kernel(const float* __restrict__ x,
                     const float* __restrict__ ln_g, const float* __restrict__ ln_b,
                     const float* __restrict__ bqkv, const float* __restrict__ bout,
                     float* __restrict__ out) {
    extern __shared__ char smc[];
    const u32 smb = smem_u32(smc);
    const int tid = threadIdx.x, wid = tid >> 5, lane = tid & 31;
    const int w = blockIdx.x, b = w >> 6, wy = (w >> 3) & 7, wx = w & 7;

    // prefetch W chunk 0 (overlaps LN below)
    cp_w(smb + OFF_W0, d_wqH, d_wqL, 384, 0, tid); CP_COMMIT();

    // zero V-tile pad rows 49..63
    if (tid < 480) {
        int t = tid, tile = t / 240, rem = t % 240;
        int row = 49 + rem / 16, q16 = (rem & 15) * 16;
        *reinterpret_cast<uint4*>(smc + OFF_V + tile * TILE + row * AST + q16) =
            make_uint4(0, 0, 0, 0);
    }
    // ---- Phase A: LayerNorm -> split-bf16 X tiles ----
    {
        float4 gg = *reinterpret_cast<const float4*>(&ln_g[lane * 4]);
        float4 bb = *reinterpret_cast<const float4*>(&ln_b[lane * 4]);
        for (int t = wid; t < 49; t += 16) {
            int r = wy * WSZ + t / WSZ, cp = wx * WSZ + t % WSZ;
            const float* xr = x + (size_t)(b * NPIX + r * HIMG + cp) * CDIM;
            float4 v = *reinterpret_cast<const float4*>(&xr[lane * 4]);
            float s = v.x + v.y + v.z + v.w;
            float q = v.x * v.x + v.y * v.y + v.z * v.z + v.w * v.w;
            #pragma unroll
            for (int o = 16; o; o >>= 1) {
                s += __shfl_xor_sync(0xffffffffu, s, o);
                q += __shfl_xor_sync(0xffffffffu, q, o);
            }
            float mu = s * (1.f / 128.f);
            float rs = rsqrtf(q * (1.f / 128.f) - mu * mu + LN_EPS);
            u32 h0, l0, h1, l1;
            split2((v.x - mu) * rs * gg.x + bb.x, (v.y - mu) * rs * gg.y + bb.y, h0, l0);
            split2((v.z - mu) * rs * gg.z + bb.z, (v.w - mu) * rs * gg.w + bb.w, h1, l1);
            char* p = smc + t * AST + lane * 8;
            *reinterpret_cast<uint2*>(p + OFF_XH) = make_uint2(h0, h1);
            *reinterpret_cast<uint2*>(p + OFF_XL) = make_uint2(l0, l1);
        }
    }

    const int mband = wid >> 2, nq = wid & 3, tig = lane & 3, g = lane >> 2;

    // ---- Phase B: QKV GEMM, 6 chunks N=64; ONE barrier per chunk ----
    // Safe distance-1 prefetch: buffer (ch+1)&1 was last read in chunk ch-1,
    // and every warp finished ch-1 before the sync at the top of chunk ch.
    for (int ch = 0; ch < 6; ++ch) {
        u32 wbase = smb + OFF_W0 + (ch & 1) * WBUFSZ;
        CP_WAIT(0);
        __syncthreads();                 // W(ch) visible to all; also LN sync at ch=0
        if (ch < 5) {
            cp_w(smb + OFF_W0 + ((ch + 1) & 1) * WBUFSZ, d_wqH, d_wqL, 384, (ch + 1) * 64, tid);
            CP_COMMIT();
        }
        float d[2][4] = {};
        gemm_chunk(smb, wbase, lane, mband, nq, d);
        int R0 = mband * 16 + g, R1 = R0 + 8;
        #pragma unroll
        for (int nt = 0; nt < 2; ++nt) {
            int n = ch * 64 + nq * 16 + nt * 8 + 2 * tig;
            int base = OFF_Q + (n >> 7) * 2 * TILE, col = n & 127;
            float2 bq = *reinterpret_cast<const float2*>(bqkv + n);
            if (R0 < 49) {
                u32 uh, ul;
                split2(d[nt][0] + bq.x, d[nt][1] + bq.y, uh, ul);
                char* p = smc + base + R0 * AST + col * 2;
                *reinterpret_cast<u32*>(p) = uh;
                *reinterpret_cast<u32*>(p + TILE) = ul;
            }
            if (R1 < 49) {
                u32 uh, ul;
                split2(d[nt][2] + bq.x, d[nt][3] + bq.y, uh, ul);
                char* p = smc + base + R1 * AST + col * 2;
                *reinterpret_cast<u32*>(p) = uh;
                *reinterpret_cast<u32*>(p + TILE) = ul;
            }
        }
    }
    // wout chunk0 -> buf0 (safe: buf0 last read in chunk 4, all warps past ch5 top sync)
    cp_w(smb + OFF_W0, d_woH, d_woL, 128, 0, tid); CP_COMMIT();
    __syncthreads();                     // QKV tiles complete
    // wout chunk1 -> buf1 (safe now: everyone done reading chunk 5)
    cp_w(smb + OFF_W0 + WBUFSZ, d_woH, d_woL, 128, 64, tid); CP_COMMIT();

    // ---- Phase C: tensor-core attention; warp = (head, 2 q-bands) ----
    {
        const int head = wid & 7, half = wid >> 3;
        #pragma unroll
        for (int band = 0; band < 2; ++band) {
            int m0 = (half * 2 + band) * 16;
            u32 qh[4], ql[4];
            u32 aaddr = smb + OFF_Q + (m0 + (lane & 15)) * AST + head * 32 + (lane >> 4) * 16;
            ldsm4(qh, aaddr);
            ldsm4(ql, aaddr + TILE);
            float sd[7][4];
            #pragma unroll
            for (int nt = 0; nt < 7; ++nt) { sd[nt][0]=sd[nt][1]=sd[nt][2]=sd[nt][3]=0.f; }
            // K non-trans x4: lanes 0-15 rows (lane&7)+0/8? -> rows pair; lanes 16-31 rows +8 for nt odd
            u32 k4addr = smb + OFF_K + (((lane >> 4) & 1) * 8 + (lane & 7)) * AST
                         + head * 32 + ((lane >> 3) & 1) * 16;
            #pragma unroll
            for (int np = 0; np < 3; ++np) {
                u32 bh[4], bl[4];
                ldsm4(bh, k4addr + np * 16 * AST);
                ldsm4(bl, k4addr + np * 16 * AST + TILE);
                mma16816(sd[2*np],   qh, bh[0], bh[1]);
                mma16816(sd[2*np],   qh, bl[0], bl[1]);
                mma16816(sd[2*np],   ql, bh[0], bh[1]);
                mma16816(sd[2*np+1], qh, bh[2], bh[3]);
                mma16816(sd[2*np+1], qh, bl[2], bl[3]);
                mma16816(sd[2*np+1], ql, bh[2], bh[3]);
            }
            {   // nt = 6 leftover (rows 48-55)
                u32 b2h[2], b2l[2];
                u32 k2addr = smb + OFF_K + (48 + (lane & 7)) * AST + head * 32 + ((lane >> 3) & 1) * 16;
                ldsm2(b2h, k2addr);
                ldsm2(b2l, k2addr + TILE);
                mma16816(sd[6], qh, b2h[0], b2h[1]);
                mma16816(sd[6], qh, b2l[0], b2l[1]);
                mma16816(sd[6], ql, b2h[0], b2h[1]);
            }
            float den0 = 0.f, den1 = 0.f;
            u32 Phg[8], Phg8[8], Plg[8], Plg8[8];
            #pragma unroll
            for (int nt = 0; nt < 7; ++nt) {
                float e0 = fexp(sd[nt][0] * SCALE_F);
                float e1 = fexp(sd[nt][1] * SCALE_F);
                float e2 = fexp(sd[nt][2] * SCALE_F);
                float e3 = fexp(sd[nt][3] * SCALE_F);
                if (nt == 6) {
                    bool v0 = tig == 0;
                    e0 = v0 ? e0 : 0.f; e2 = v0 ? e2 : 0.f;
                    e1 = 0.f; e3 = 0.f;
                }
                den0 += e0 + e1; den1 += e2 + e3;
                split2(e0, e1, Phg[nt], Plg[nt]);
                split2(e2, e3, Phg8[nt], Plg8[nt]);
            }
            Phg[7] = Plg[7] = Phg8[7] = Plg8[7] = 0u;
            den0 += __shfl_xor_sync(0xffffffffu, den0, 1);
            den0 += __shfl_xor_sync(0xffffffffu, den0, 2);
            den1 += __shfl_xor_sync(0xffffffffu, den1, 1);
            den1 += __shfl_xor_sync(0xffffffffu, den1, 2);
            float od[2][4] = {};
            #pragma unroll
            for (int kc = 0; kc < 4; ++kc) {
                u32 ah[4] = {Phg[2*kc], Phg8[2*kc], Phg[2*kc+1], Phg8[2*kc+1]};
                u32 al[4] = {Plg[2*kc], Plg8[2*kc], Plg[2*kc+1], Plg8[2*kc+1]};
                // V trans x4: lanes 0-15 rows kc*16+(lane&15); lanes 16-31 same rows col +8
                u32 v4addr = smb + OFF_V + (kc * 16 + (lane & 15)) * AST + head * 32 + (lane >> 4) * 16;
                u32 vh[4], vl[4];
                ldsm4t(vh, v4addr);
                ldsm4t(vl, v4addr + TILE);
                #pragma unroll
                for (int ntO = 0; ntO < 2; ++ntO) {
                    mma16816(od[ntO], ah, vh[2*ntO], vh[2*ntO+1]);
                    mma16816(od[ntO], ah, vl[2*ntO], vl[2*ntO+1]);
                    mma16816(od[ntO], al, vh[2*ntO], vh[2*ntO+1]);
                }
            }
            float inv0 = __frcp_rn(den0), inv1 = __frcp_rn(den1);
            int r0 = m0 + g, r1 = r0 + 8;
            #pragma unroll
            for (int ntO = 0; ntO < 2; ++ntO) {
                int col = head * 16 + ntO * 8 + 2 * tig;
                if (r0 < 49) {
                    u32 uh, ul;
                    split2(od[ntO][0] * inv0, od[ntO][1] * inv0, uh, ul);
                    char* p = smc + r0 * AST + col * 2;
                    *reinterpret_cast<u32*>(p + OFF_XH) = uh;
                    *reinterpret_cast<u32*>(p + OFF_XL) = ul;
                }
                if (r1 < 49) {
                    u32 uh, ul;
                    split2(od[ntO][2] * inv1, od[ntO][3] * inv1, uh, ul);
                    char* p = smc + r1 * AST + col * 2;
                    *reinterpret_cast<u32*>(p + OFF_XH) = uh;
                    *reinterpret_cast<u32*>(p + OFF_XL) = ul;
                }
            }
        }
    }
    CP_WAIT(0);
    __syncthreads();

    // ---- Phase D: out-proj, both chunks resident; no inner barriers ----
    #pragma unroll
    for (int ch = 0; ch < 2; ++ch) {
        float d[2][4] = {};
        gemm_chunk(smb, smb + OFF_W0 + ch * WBUFSZ, lane, mband, nq, d);
        int R0 = mband * 16 + g, R1 = R0 + 8;
        #pragma unroll
        for (int nt = 0; nt < 2; ++nt) {
            int n = ch * 64 + nq * 16 + nt * 8 + 2 * tig;
            float2 bo = *reinterpret_cast<const float2*>(bout + n);
            if (R0 < 49) {
                int r = wy * WSZ + R0 / WSZ, cp = wx * WSZ + R0 % WSZ;
                *reinterpret_cast<float2*>(out + (size_t)(b * NPIX + r * HIMG + cp) * CDIM + n) =
                    make_float2(d[nt][0] + bo.x, d[nt][1] + bo.y);
            }
            if (R1 < 49) {
                int r = wy * WSZ + R1 / WSZ, cp = wx * WSZ + R1 % WSZ;
                *reinterpret_cast<float2*>(out + (size_t)(b * NPIX + r * HIMG + cp) * CDIM + n) =
                    make_float2(d[nt][2] + bo.x, d[nt][3] + bo.y);
            }
        }
    }
}

extern "C" void kernel_launch(void* const* d_in, const int* in_sizes, int n_in,
                              void* d_out, int out_size) {
    const float* x    = (const float*)d_in[0];
    const float* g    = (const float*)d_in[1];
    const float* bt   = (const float*)d_in[2];
    const float* wqkv = (const float*)d_in[3];
    const float* bqkv = (const float*)d_in[4];
    const float* wout = (const float*)d_in[5];
    const float* bout = (const float*)d_in[6];
    float* out = (float*)d_out;
    prep_w_kernel<<<256, 256>>>(wqkv, wout);
    cudaFuncSetAttribute(swin_mma_kernel,
                         cudaFuncAttributeMaxDynamicSharedMemorySize, SMEM_BYTES);
    swin_mma_kernel<<<4096, TPB, SMEM_BYTES>>>(x, g, bt, bqkv, bout, out);
}